// round 4
// baseline (speedup 1.0000x reference)
#include <cuda_runtime.h>
#include <cuda_bf16.h>
#include <cstdint>

// ---------------------------------------------------------------------------
// Problem constants
// ---------------------------------------------------------------------------
#define B_   4
#define T_   1024
#define C_   2048
#define NH   16
#define NKV  4
#define HD   128
#define M_   (B_ * T_)            // 4096 rows
#define QDIM (NH * HD)            // 2048
#define KDIM (NKV * HD)           // 512

// Scratch (device globals; no allocation allowed)
__device__ float g_q   [M_ * QDIM];     // 32 MB
__device__ float g_k   [M_ * KDIM];     // 8 MB
__device__ float g_v   [M_ * KDIM];     // 8 MB
__device__ float g_ao  [M_ * QDIM];     // 32 MB
__device__ float g_ahi [M_ * C_];       // 32 MB  (activation tf32 hi)
__device__ float g_alo [M_ * C_];       // 32 MB  (activation tf32 lo)
__device__ float g_wthi[C_ * C_];       // 16 MB  (transposed weight tf32 hi)
__device__ float g_wtlo[C_ * C_];       // 16 MB  (transposed weight tf32 lo)

typedef unsigned long long ull;

// ---------------------------------------------------------------------------
// f32x2 packed-FMA helpers
// ---------------------------------------------------------------------------
__device__ __forceinline__ ull pk2(float x, float y) {
    ull r; asm("mov.b64 %0, {%1, %2};" : "=l"(r) : "f"(x), "f"(y)); return r;
}
__device__ __forceinline__ void fma2(ull& c, ull a, ull b) {
    asm("fma.rn.f32x2 %0, %1, %2, %0;" : "+l"(c) : "l"(a), "l"(b));
}
__device__ __forceinline__ void mul2(ull& c, ull a) {
    asm("mul.rn.f32x2 %0, %0, %1;" : "+l"(c) : "l"(a));
}
__device__ __forceinline__ float2 upk(ull v) {
    float2 r; asm("mov.b64 {%0, %1}, %2;" : "=f"(r.x), "=f"(r.y) : "l"(v)); return r;
}

// ---------------------------------------------------------------------------
// tf32 hi/lo split
// ---------------------------------------------------------------------------
__device__ __forceinline__ void tf32_split(float a, float& h, float& l) {
    uint32_t u;
    asm("cvt.rna.tf32.f32 %0, %1;" : "=r"(u) : "f"(a));
    h = __uint_as_float(u);
    float r = a - h;
    asm("cvt.rna.tf32.f32 %0, %1;" : "=r"(u) : "f"(r));
    l = __uint_as_float(u);
}

// Elementwise hi/lo split (float4)
__global__ void conv_hilo(const float* __restrict__ src,
                          float* __restrict__ hi, float* __restrict__ lo)
{
    int i = blockIdx.x * 256 + threadIdx.x;
    float4 a = ((const float4*)src)[i];
    float4 h, l;
    tf32_split(a.x, h.x, l.x);  tf32_split(a.y, h.y, l.y);
    tf32_split(a.z, h.z, l.z);  tf32_split(a.w, h.w, l.w);
    ((float4*)hi)[i] = h;  ((float4*)lo)[i] = l;
}

// Transpose [K2,N2] -> [N2,K2] with hi/lo split (output leading dim C_)
__global__ void tconv(const float* __restrict__ W,
                      float* __restrict__ thi, float* __restrict__ tlo, int N2)
{
    __shared__ float tile[32][33];
    const int bx = blockIdx.x * 32;   // N2 dim
    const int by = blockIdx.y * 32;   // K2 dim
    const int tx = threadIdx.x, ty = threadIdx.y;
    #pragma unroll
    for (int j = 0; j < 32; j += 8)
        tile[ty + j][tx] = W[(size_t)(by + ty + j) * N2 + bx + tx];
    __syncthreads();
    #pragma unroll
    for (int j = 0; j < 32; j += 8) {
        float a = tile[tx][ty + j];
        float h, l; tf32_split(a, h, l);
        size_t o = (size_t)(bx + ty + j) * C_ + by + tx;
        thi[o] = h;  tlo[o] = l;
    }
}

// ---------------------------------------------------------------------------
// mma.sync tf32 3xTF32 GEMM: C[M,N] = A[M,2048] @ Wt[N,2048]^T
// 128x128 block tile, BK=16, 8 warps (2x4), warp tile 64x32.
// Fragment-packed shared memory: one LDS.128 per A-frag, LDS.64 per B-frag.
// ---------------------------------------------------------------------------
#define BMT 128
#define BNT 128
#define BKT 16
#define NCH2 (C_ / BKT)           // 128 chunks
#define AH_OFF 0
#define AL_OFF 2048
#define BH_OFF 4096
#define BL_OFF 6144
#define STG_FLOATS 8192           // 32 KB per stage
#define GSMEM_TOTAL (2 * STG_FLOATS * 4)   // 64 KB

#define MMA_TF32(c, A4, B2) \
    asm volatile( \
        "mma.sync.aligned.m16n8k8.row.col.f32.tf32.tf32.f32 " \
        "{%0,%1,%2,%3}, {%4,%5,%6,%7}, {%8,%9}, {%0,%1,%2,%3};" \
        : "+f"((c)[0]), "+f"((c)[1]), "+f"((c)[2]), "+f"((c)[3]) \
        : "r"(__float_as_uint((A4).x)), "r"(__float_as_uint((A4).y)), \
          "r"(__float_as_uint((A4).z)), "r"(__float_as_uint((A4).w)), \
          "r"(__float_as_uint((B2).x)), "r"(__float_as_uint((B2).y)))

extern __shared__ float smf[];

__global__ void __launch_bounds__(256, 1)
gemm_mma(const float* __restrict__ Ahi, const float* __restrict__ Alo,
         const float* __restrict__ Bhi, const float* __restrict__ Blo,
         float* __restrict__ C, int N)
{
    const int tid  = threadIdx.x;
    const int lane = tid & 31;
    const int wid  = tid >> 5;
    const int wm   = wid >> 2;       // 0..1  (64 rows each)
    const int wn   = wid & 3;        // 0..3  (32 cols each)
    const int bm   = blockIdx.y * BMT;
    const int bn   = blockIdx.x * BNT;

    // ---- staging assignment (two (row,q) pairs per thread, fixed) ----
    const int row0 = tid >> 2;           // 0..63
    const int row1 = row0 + 64;          // 64..127
    const int q    = tid & 3;            // k4 index 0..3

    // fragment scatter destination offsets (floats), constant per thread
    auto aoff = [](int row, int qq) {
        int K = qq >> 1, c4 = qq & 1, Mi = row >> 4, r = row & 15;
        int reg = (c4 << 1) | (r >> 3);
        return (K * 8 + Mi) * 128 + (r & 7) * 4 + reg;
    };
    auto boff = [](int row, int qq) {
        int K = qq >> 1, reg = qq & 1, Ni = row >> 3, rn = row & 7;
        return (K * 16 + Ni) * 64 + rn * 2 + reg;
    };
    const int aOff0 = aoff(row0, q), aOff1 = aoff(row1, q);
    const int bOff0 = boff(row0, q), bOff1 = boff(row1, q);

    const float* gAh0 = Ahi + (size_t)(bm + row0) * C_ + q * 4;
    const float* gAl0 = Alo + (size_t)(bm + row0) * C_ + q * 4;
    const float* gAh1 = Ahi + (size_t)(bm + row1) * C_ + q * 4;
    const float* gAl1 = Alo + (size_t)(bm + row1) * C_ + q * 4;
    const float* gBh0 = Bhi + (size_t)(bn + row0) * C_ + q * 4;
    const float* gBl0 = Blo + (size_t)(bn + row0) * C_ + q * 4;
    const float* gBh1 = Bhi + (size_t)(bn + row1) * C_ + q * 4;
    const float* gBl1 = Blo + (size_t)(bn + row1) * C_ + q * 4;

    float acc[4][4][4];
    #pragma unroll
    for (int a = 0; a < 4; ++a)
        #pragma unroll
        for (int b = 0; b < 4; ++b)
            #pragma unroll
            for (int r = 0; r < 4; ++r) acc[a][b][r] = 0.0f;

    float4 pAh0, pAl0, pAh1, pAl1, pBh0, pBl0, pBh1, pBl1;

    // prologue: fetch chunk 0
    pAh0 = *(const float4*)(gAh0);  pAl0 = *(const float4*)(gAl0);
    pAh1 = *(const float4*)(gAh1);  pAl1 = *(const float4*)(gAl1);
    pBh0 = *(const float4*)(gBh0);  pBl0 = *(const float4*)(gBl0);
    pBh1 = *(const float4*)(gBh1);  pBl1 = *(const float4*)(gBl1);

    // stage chunk 0 into buffer 0
    {
        float* buf = smf;
        float* d;
        d = buf + AH_OFF + aOff0; d[0]=pAh0.x; d[32]=pAh0.y; d[64]=pAh0.z; d[96]=pAh0.w;
        d = buf + AL_OFF + aOff0; d[0]=pAl0.x; d[32]=pAl0.y; d[64]=pAl0.z; d[96]=pAl0.w;
        d = buf + AH_OFF + aOff1; d[0]=pAh1.x; d[32]=pAh1.y; d[64]=pAh1.z; d[96]=pAh1.w;
        d = buf + AL_OFF + aOff1; d[0]=pAl1.x; d[32]=pAl1.y; d[64]=pAl1.z; d[96]=pAl1.w;
        d = buf + BH_OFF + bOff0; d[0]=pBh0.x; d[16]=pBh0.y; d[32]=pBh0.z; d[48]=pBh0.w;
        d = buf + BL_OFF + bOff0; d[0]=pBl0.x; d[16]=pBl0.y; d[32]=pBl0.z; d[48]=pBl0.w;
        d = buf + BH_OFF + bOff1; d[0]=pBh1.x; d[16]=pBh1.y; d[32]=pBh1.z; d[48]=pBh1.w;
        d = buf + BL_OFF + bOff1; d[0]=pBl1.x; d[16]=pBl1.y; d[32]=pBl1.z; d[48]=pBl1.w;
    }
    __syncthreads();

    const int pl = (lane & 3) * 8 + (lane >> 2);   // transposed frag slot

    for (int c = 0; c < NCH2; ++c) {
        // fetch next chunk into registers (overlaps with compute)
        if (c + 1 < NCH2) {
            const int k0 = (c + 1) * BKT;
            pAh0 = *(const float4*)(gAh0 + k0);  pAl0 = *(const float4*)(gAl0 + k0);
            pAh1 = *(const float4*)(gAh1 + k0);  pAl1 = *(const float4*)(gAl1 + k0);
            pBh0 = *(const float4*)(gBh0 + k0);  pBl0 = *(const float4*)(gBl0 + k0);
            pBh1 = *(const float4*)(gBh1 + k0);  pBl1 = *(const float4*)(gBl1 + k0);
        }

        // consume current buffer
        {
            const float* buf = smf + (c & 1) * STG_FLOATS;
            #pragma unroll
            for (int K = 0; K < 2; ++K) {
                float4 AH[4], AL[4];
                float2 BH[4], BL[4];
                #pragma unroll
                for (int a = 0; a < 4; ++a) {
                    int blk = (K * 8 + wm * 4 + a) * 128 + pl * 4;
                    AH[a] = *(const float4*)(buf + AH_OFF + blk);
                    AL[a] = *(const float4*)(buf + AL_OFF + blk);
                }
                #pragma unroll
                for (int b = 0; b < 4; ++b) {
                    int blk = (K * 16 + wn * 4 + b) * 64 + pl * 2;
                    BH[b] = *(const float2*)(buf + BH_OFF + blk);
                    BL[b] = *(const float2*)(buf + BL_OFF + blk);
                }
                #pragma unroll
                for (int a = 0; a < 4; ++a)
                    #pragma unroll
                    for (int b = 0; b < 4; ++b) {
                        MMA_TF32(acc[a][b], AH[a], BH[b]);
                        MMA_TF32(acc[a][b], AH[a], BL[b]);
                        MMA_TF32(acc[a][b], AL[a], BH[b]);
                    }
            }
        }

        // stage next chunk into other buffer
        if (c + 1 < NCH2) {
            float* buf = smf + ((c + 1) & 1) * STG_FLOATS;
            float* d;
            d = buf + AH_OFF + aOff0; d[0]=pAh0.x; d[32]=pAh0.y; d[64]=pAh0.z; d[96]=pAh0.w;
            d = buf + AL_OFF + aOff0; d[0]=pAl0.x; d[32]=pAl0.y; d[64]=pAl0.z; d[96]=pAl0.w;
            d = buf + AH_OFF + aOff1; d[0]=pAh1.x; d[32]=pAh1.y; d[64]=pAh1.z; d[96]=pAh1.w;
            d = buf + AL_OFF + aOff1; d[0]=pAl1.x; d[32]=pAl1.y; d[64]=pAl1.z; d[96]=pAl1.w;
            d = buf + BH_OFF + bOff0; d[0]=pBh0.x; d[16]=pBh0.y; d[32]=pBh0.z; d[48]=pBh0.w;
            d = buf + BL_OFF + bOff0; d[0]=pBl0.x; d[16]=pBl0.y; d[32]=pBl0.z; d[48]=pBl0.w;
            d = buf + BH_OFF + bOff1; d[0]=pBh1.x; d[16]=pBh1.y; d[32]=pBh1.z; d[48]=pBh1.w;
            d = buf + BL_OFF + bOff1; d[0]=pBl1.x; d[16]=pBl1.y; d[32]=pBl1.z; d[48]=pBl1.w;
        }
        __syncthreads();
    }

    // ---- epilogue ----
    const int g  = lane >> 2;
    const int t4 = lane & 3;
    #pragma unroll
    for (int a = 0; a < 4; ++a) {
        #pragma unroll
        for (int b = 0; b < 4; ++b) {
            int r0 = bm + wm * 64 + a * 16 + g;
            int cc = bn + wn * 32 + b * 8 + t4 * 2;
            *(float2*)&C[(size_t)r0 * N + cc] =
                make_float2(acc[a][b][0], acc[a][b][1]);
            *(float2*)&C[(size_t)(r0 + 8) * N + cc] =
                make_float2(acc[a][b][2], acc[a][b][3]);
        }
    }
}

// ---------------------------------------------------------------------------
// Fused RoPE + RMSNorm (unchanged, known-good)
// ---------------------------------------------------------------------------
__global__ void rope_rms_kernel(float* __restrict__ q, float* __restrict__ k,
                                const float* __restrict__ cosp,
                                const float* __restrict__ sinp)
{
    const int bt = blockIdx.x;
    const int h  = blockIdx.y;
    const int t  = bt & (T_ - 1);
    const int i  = threadIdx.x;

    float* row = (h < NH)
        ? (q + (size_t)bt * QDIM + h * HD)
        : (k + (size_t)bt * KDIM + (h - NH) * HD);

    float x1 = row[i];
    float x2 = row[i + 64];
    float c  = cosp[t * 64 + i];
    float s  = sinp[t * 64 + i];
    float y1 = x1 * c - x2 * s;
    float y2 = x1 * s + x2 * c;

    float ss = y1 * y1 + y2 * y2;
    #pragma unroll
    for (int off = 16; off > 0; off >>= 1)
        ss += __shfl_xor_sync(0xffffffffu, ss, off);

    __shared__ float wsum[2];
    if ((i & 31) == 0) wsum[i >> 5] = ss;
    __syncthreads();
    float tot = wsum[0] + wsum[1];
    float rn  = rsqrtf(tot * (1.0f / 128.0f) + 1e-6f);

    row[i]      = y1 * rn;
    row[i + 64] = y2 * rn;
}

// ---------------------------------------------------------------------------
// Flash attention (causal, GQA 4:1), fp32, f32x2 — unchanged, known-good
// ---------------------------------------------------------------------------
struct AttnSmem {
    float Q[64][132];
    float K[64][132];
    float V[64][132];
    float P[64][68];
    float m[64];
    float l[64];
    float al[64];
};

extern __shared__ char attn_smem_raw[];

__global__ void __launch_bounds__(256)
attn_kernel(const float* __restrict__ q, const float* __restrict__ k,
            const float* __restrict__ v, float* __restrict__ o)
{
    AttnSmem& S = *reinterpret_cast<AttnSmem*>(attn_smem_raw);
    const int qt  = blockIdx.x;
    const int h   = blockIdx.y;
    const int b   = blockIdx.z;
    const int kvh = h >> 2;
    const int tid = threadIdx.x;
    const int tx  = tid & 15;
    const int ty  = tid >> 4;

    const int r0 = tid >> 5;
    const int d4 = (tid & 31) * 4;

    const float* qbase = q + (size_t)(b * T_ + qt * 64) * QDIM + h * HD;
    #pragma unroll
    for (int it = 0; it < 8; ++it) {
        int r = r0 + it * 8;
        *(float4*)&S.Q[r][d4] = *(const float4*)(qbase + (size_t)r * QDIM + d4);
    }
    if (tid < 64) { S.m[tid] = -1e30f; S.l[tid] = 0.0f; }

    ull oacc2[4][4];
    #pragma unroll
    for (int i = 0; i < 4; ++i)
        #pragma unroll
        for (int j = 0; j < 4; ++j) oacc2[i][j] = 0ull;

    const float scale = 0.08838834764831845f;

    for (int kt = 0; kt <= qt; ++kt) {
        __syncthreads();
        const float* kbase = k + (size_t)(b * T_ + kt * 64) * KDIM + kvh * HD;
        const float* vbase = v + (size_t)(b * T_ + kt * 64) * KDIM + kvh * HD;
        #pragma unroll
        for (int it = 0; it < 8; ++it) {
            int r = r0 + it * 8;
            *(float4*)&S.K[r][d4] = *(const float4*)(kbase + (size_t)r * KDIM + d4);
            *(float4*)&S.V[r][d4] = *(const float4*)(vbase + (size_t)r * KDIM + d4);
        }
        __syncthreads();

        ull sacc2[4][4];
        #pragma unroll
        for (int i = 0; i < 4; ++i)
            #pragma unroll
            for (int j = 0; j < 4; ++j) sacc2[i][j] = 0ull;

        #pragma unroll 8
        for (int kk = 0; kk < 128; kk += 2) {
            ull qf2[4], kf2[4];
            #pragma unroll
            for (int i = 0; i < 4; ++i)
                qf2[i] = *(const ull*)&S.Q[ty + 16 * i][kk];
            #pragma unroll
            for (int j = 0; j < 4; ++j)
                kf2[j] = *(const ull*)&S.K[tx + 16 * j][kk];
            #pragma unroll
            for (int i = 0; i < 4; ++i)
                #pragma unroll
                for (int j = 0; j < 4; ++j)
                    fma2(sacc2[i][j], qf2[i], kf2[j]);
        }

        const bool diag = (kt == qt);
        #pragma unroll
        for (int i = 0; i < 4; ++i) {
            int rr = ty + 16 * i;
            #pragma unroll
            for (int j = 0; j < 4; ++j) {
                int cc = tx + 16 * j;
                float2 sp = upk(sacc2[i][j]);
                float sv = (sp.x + sp.y) * scale;
                if (diag && cc > rr) sv = -1e30f;
                S.P[rr][cc] = sv;
            }
        }
        __syncthreads();

        {
            int row = tid >> 2, qq = tid & 3;
            float mloc = -1e30f;
            #pragma unroll
            for (int c = 0; c < 16; ++c)
                mloc = fmaxf(mloc, S.P[row][qq * 16 + c]);
            mloc = fmaxf(mloc, __shfl_xor_sync(0xffffffffu, mloc, 1));
            mloc = fmaxf(mloc, __shfl_xor_sync(0xffffffffu, mloc, 2));
            float mo = S.m[row];
            float mn = fmaxf(mo, mloc);
            float sum = 0.0f;
            #pragma unroll
            for (int c = 0; c < 16; ++c) {
                int idx = qq * 16 + c;
                float p = __expf(S.P[row][idx] - mn);
                S.P[row][idx] = p;
                sum += p;
            }
            sum += __shfl_xor_sync(0xffffffffu, sum, 1);
            sum += __shfl_xor_sync(0xffffffffu, sum, 2);
            if (qq == 0) {
                float a = __expf(mo - mn);
                S.al[row] = a;
                S.l[row]  = S.l[row] * a + sum;
                S.m[row]  = mn;
            }
        }
        __syncthreads();

        #pragma unroll
        for (int i = 0; i < 4; ++i) {
            float a = S.al[ty + 16 * i];
            ull a2 = pk2(a, a);
            #pragma unroll
            for (int j = 0; j < 4; ++j) mul2(oacc2[i][j], a2);
        }

        #pragma unroll 4
        for (int kc = 0; kc < 64; ++kc) {
            ull pv2[4], vv2[4];
            #pragma unroll
            for (int i = 0; i < 4; ++i) {
                float p = S.P[ty + 16 * i][kc];
                pv2[i] = pk2(p, p);
            }
            #pragma unroll
            for (int j = 0; j < 4; ++j)
                vv2[j] = *(const ull*)&S.V[kc][tx * 2 + 32 * j];
            #pragma unroll
            for (int i = 0; i < 4; ++i)
                #pragma unroll
                for (int j = 0; j < 4; ++j)
                    fma2(oacc2[i][j], pv2[i], vv2[j]);
        }
    }

    #pragma unroll
    for (int i = 0; i < 4; ++i) {
        int r = ty + 16 * i;
        float inv = 1.0f / S.l[r];
        size_t rowoff = (size_t)(b * T_ + qt * 64 + r) * QDIM + h * HD;
        #pragma unroll
        for (int j = 0; j < 4; ++j) {
            float2 c = upk(oacc2[i][j]);
            *(float2*)&o[rowoff + tx * 2 + 32 * j] =
                make_float2(c.x * inv, c.y * inv);
        }
    }
}

// ---------------------------------------------------------------------------
// Launch
// ---------------------------------------------------------------------------
extern "C" void kernel_launch(void* const* d_in, const int* in_sizes, int n_in,
                              void* d_out, int out_size)
{
    const float* x    = (const float*)d_in[0];
    const float* cosp = (const float*)d_in[1];
    const float* sinp = (const float*)d_in[2];
    const float* Wq   = (const float*)d_in[3];
    const float* Wk   = (const float*)d_in[4];
    const float* Wv   = (const float*)d_in[5];
    const float* Wo   = (const float*)d_in[6];
    float* out        = (float*)d_out;

    float *qb, *kb, *vb, *aob, *ahi, *alo, *wthi, *wtlo;
    cudaGetSymbolAddress((void**)&qb,   g_q);
    cudaGetSymbolAddress((void**)&kb,   g_k);
    cudaGetSymbolAddress((void**)&vb,   g_v);
    cudaGetSymbolAddress((void**)&aob,  g_ao);
    cudaGetSymbolAddress((void**)&ahi,  g_ahi);
    cudaGetSymbolAddress((void**)&alo,  g_alo);
    cudaGetSymbolAddress((void**)&wthi, g_wthi);
    cudaGetSymbolAddress((void**)&wtlo, g_wtlo);

    cudaFuncSetAttribute(attn_kernel,
                         cudaFuncAttributeMaxDynamicSharedMemorySize,
                         (int)sizeof(AttnSmem));
    cudaFuncSetAttribute(gemm_mma,
                         cudaFuncAttributeMaxDynamicSharedMemorySize,
                         GSMEM_TOTAL);

    const int NELEM4 = M_ * C_ / 4;

    // x -> hi/lo
    conv_hilo<<<NELEM4 / 256, 256>>>(x, ahi, alo);

    // Q projection
    tconv<<<dim3(QDIM / 32, C_ / 32), dim3(32, 8)>>>(Wq, wthi, wtlo, QDIM);
    gemm_mma<<<dim3(QDIM / BNT, M_ / BMT), 256, GSMEM_TOTAL>>>(ahi, alo, wthi, wtlo, qb, QDIM);

    // K projection
    tconv<<<dim3(KDIM / 32, C_ / 32), dim3(32, 8)>>>(Wk, wthi, wtlo, KDIM);
    gemm_mma<<<dim3(KDIM / BNT, M_ / BMT), 256, GSMEM_TOTAL>>>(ahi, alo, wthi, wtlo, kb, KDIM);

    // V projection
    tconv<<<dim3(KDIM / 32, C_ / 32), dim3(32, 8)>>>(Wv, wthi, wtlo, KDIM);
    gemm_mma<<<dim3(KDIM / BNT, M_ / BMT), 256, GSMEM_TOTAL>>>(ahi, alo, wthi, wtlo, vb, KDIM);

    // RoPE + RMSNorm
    rope_rms_kernel<<<dim3(M_, NH + NKV), 64>>>(qb, kb, cosp, sinp);

    // Attention
    attn_kernel<<<dim3(T_ / 64, NH, B_), 256, sizeof(AttnSmem)>>>(qb, kb, vb, aob);

    // Output projection
    conv_hilo<<<NELEM4 / 256, 256>>>(aob, ahi, alo);
    tconv<<<dim3(QDIM / 32, C_ / 32), dim3(32, 8)>>>(Wo, wthi, wtlo, QDIM);
    gemm_mma<<<dim3(QDIM / BNT, M_ / BMT), 256, GSMEM_TOTAL>>>(ahi, alo, wthi, wtlo, out, QDIM);
}